// round 5
// baseline (speedup 1.0000x reference)
#include <cuda_runtime.h>
#include <math.h>

typedef unsigned long long ull;

// ---- geometry ----
#define TBATCH 8          // graphs per CTA
#define NW 8              // warps per CTA (each warp = 1 graph = 6 rows)
#define THREADS 256
#define LDBB 512          // row stride: 128 floats * 4B
#define ROWSB 3072        // 6 rows * 512 B per warp
#define B0A 0
#define B1A 24576
#define B2A 49152
#define XSA 73728         // 8*18 floats
#define RSA 74304         // 8*12 floats
#define SMEMB 74688

// ---- repacked-weight scratch (k-pair interleaved: dst[p*256 + c*2 + par] = w[2p+par][c]) ----
#define RPO_E1W2   0
#define RPO_E2W1   16384
#define RPO_E2W2   49152
#define RPO_E3W1   65536
#define RPO_E3W2   81920
#define RPO_E4W1   98304
#define RPO_E4W2   131072
#define RPO_DMW2   147456
#define RPO_DOW1B  180224
#define RPO_DOW2   196608
#define RP_FLOATS  212992
__device__ float4 g_rp[RP_FLOATS / 4];

struct Params {
    const float *x;
    const float *e1w1,*e1b1,*e1w2,*e1b2;
    const float *e2w1,*e2b1,*e2w2,*e2b2;
    const float *e3w1,*e3b1,*e3w2,*e3b2;
    const float *e4w1,*e4b1,*e4w2,*e4b2;
    const float *ew_out,*eb_out;
    const float *dmw1,*dmb1,*dmw2,*dmb2;
    const float *dow1,*dob1,*dow2,*dob2,*dow3,*dob3;
    float *out;
};

struct Offs { unsigned a[6]; };

// ---- low-level helpers ----
__device__ __forceinline__ unsigned smem_u32(const void* p){
    unsigned r;
    asm("{ .reg .u64 t; cvta.to.shared.u64 t, %1; cvt.u32.u64 %0, t; }" : "=r"(r) : "l"(p));
    return r;
}
__device__ __forceinline__ ull pk2(float lo, float hi){
    ull r;
    asm("mov.b64 %0, {%1,%2};" : "=l"(r) : "r"(__float_as_uint(lo)), "r"(__float_as_uint(hi)));
    return r;
}
__device__ __forceinline__ void fma2(ull& d, ull a, ull b){
    asm("fma.rn.f32x2 %0, %1, %2, %0;" : "+l"(d) : "l"(a), "l"(b));
}
__device__ __forceinline__ void upk2(ull v, float& lo, float& hi){
    unsigned l,h;
    asm("mov.b64 {%0,%1}, %2;" : "=r"(l), "=r"(h) : "l"(v));
    lo = __uint_as_float(l); hi = __uint_as_float(h);
}
__device__ __forceinline__ float lds(unsigned a){
    float v; asm volatile("ld.shared.f32 %0, [%1];" : "=f"(v) : "r"(a)); return v;
}
__device__ __forceinline__ ull lds64(unsigned a){
    ull v; asm volatile("ld.shared.b64 %0, [%1];" : "=l"(v) : "r"(a)); return v;
}
__device__ __forceinline__ void sts(unsigned a, float v){
    asm volatile("st.shared.f32 [%0], %1;" :: "r"(a), "f"(v));
}
__device__ __forceinline__ void stsv4(unsigned a, float x, float y, float z, float w){
    asm volatile("st.shared.v4.f32 [%0], {%1,%2,%3,%4};" :: "r"(a), "f"(x), "f"(y), "f"(z), "f"(w));
}
__device__ __forceinline__ float4 ldsv4(unsigned a){
    float4 v;
    asm volatile("ld.shared.v4.f32 {%0,%1,%2,%3}, [%4];"
                 : "=f"(v.x), "=f"(v.y), "=f"(v.z), "=f"(v.w) : "r"(a));
    return v;
}

// ---- one k-pair: 6 rows x 4 cols, zero packing instructions ----
// wa.x = {w_k[c0],w_k1[c0]}, wa.y = {.. c1}, wb.x = c2, wb.y = c3
__device__ __forceinline__ void kpair(const unsigned* ra, int kp,
                                      ulonglong2 wa, ulonglong2 wb, ull* acc){
    #pragma unroll
    for (int r = 0; r < 6; ++r){
        ull ap = lds64(ra[r] + 8u*kp);   // {a_k, a_k+1} straight from smem
        fma2(acc[r*4+0], ap, wa.x);
        fma2(acc[r*4+1], ap, wa.y);
        fma2(acc[r*4+2], ap, wb.x);
        fma2(acc[r*4+3], ap, wb.y);
    }
}

// ---- GEMM cores ----
// big-K (repacked weights, K even), software-pipelined weight loads.
// Repacked pair = 256 floats = 64 ulonglong2 -> per-kp stride is 64 (NOT 32: R4 bug).
__device__ __forceinline__ void gemm_big(const unsigned* ra, const float* __restrict__ Wrp, int K,
                                         ull* acc, int lane){
    const ulonglong2* Wp = reinterpret_cast<const ulonglong2*>(Wrp) + 2*lane;
    ulonglong2 wa = __ldg(Wp), wb = __ldg(Wp + 1);
    int kp = 0, KP = K >> 1;
    for (; kp + 1 < KP; ++kp){
        ulonglong2 na = __ldg(Wp + 64);
        ulonglong2 nb = __ldg(Wp + 65);
        Wp += 64;
        kpair(ra, kp, wa, wb, acc);
        wa = na; wb = nb;
    }
    kpair(ra, kp, wa, wb, acc);
}

// small-K (x-based, non-repacked [K,128] weights): contribute to lo halves only
__device__ __forceinline__ void gemm_small(const unsigned* ra, const float* __restrict__ W, int K,
                                           ull* acc, int lane){
    const float4* Wp = reinterpret_cast<const float4*>(W) + lane;
    for (int k = 0; k < K; ++k){
        float4 wv = __ldg(Wp); Wp += 32;
        ull b0 = pk2(wv.x, 0.f), b1 = pk2(wv.y, 0.f);
        ull b2 = pk2(wv.z, 0.f), b3 = pk2(wv.w, 0.f);
        #pragma unroll
        for (int r = 0; r < 6; ++r){
            float a = lds(ra[r] + 4u*k);
            ull ap = pk2(a, a);
            fma2(acc[r*4+0], ap, b0); fma2(acc[r*4+1], ap, b1);
            fma2(acc[r*4+2], ap, b2); fma2(acc[r*4+3], ap, b3);
        }
    }
}

// act: 0 = ELU, 1 = ReLU, 2 = rel*ReLU (init), 3 = += rel*ReLU (accumulate)
// KA<=8 -> small path (raw weights); KA>8 -> repacked. KB (if >0) always repacked.
__device__ __noinline__ void layer(Offs oa, const float* __restrict__ WA, int KA,
                                   Offs ob, const float* __restrict__ WB, int KB,
                                   const float* __restrict__ bias, unsigned outaddr,
                                   int act, unsigned reladdr, int lane)
{
    ull acc[24];
    #pragma unroll
    for (int i = 0; i < 24; ++i) acc[i] = 0ull;

    unsigned ra[6];
    #pragma unroll
    for (int i = 0; i < 6; ++i) ra[i] = oa.a[i];
    if (KA <= 8) gemm_small(ra, WA, KA, acc, lane);
    else         gemm_big(ra, WA, KA, acc, lane);
    if (KB > 0){
        #pragma unroll
        for (int i = 0; i < 6; ++i) ra[i] = ob.a[i];
        gemm_big(ra, WB, KB, acc, lane);
    }

    float4 bv = __ldg(reinterpret_cast<const float4*>(bias) + lane);
    #pragma unroll
    for (int r = 0; r < 6; ++r){
        float l0,h0,l1,h1,l2,h2,l3,h3;
        upk2(acc[r*4+0], l0, h0); upk2(acc[r*4+1], l1, h1);
        upk2(acc[r*4+2], l2, h2); upk2(acc[r*4+3], l3, h3);
        float v0 = l0 + h0 + bv.x, v1 = l1 + h1 + bv.y;
        float v2 = l2 + h2 + bv.z, v3 = l3 + h3 + bv.w;
        unsigned oaddr = outaddr + (unsigned)(r*LDBB) + 16u*lane;
        if (act == 0){
            v0 = v0 > 0.f ? v0 : expm1f(v0);
            v1 = v1 > 0.f ? v1 : expm1f(v1);
            v2 = v2 > 0.f ? v2 : expm1f(v2);
            v3 = v3 > 0.f ? v3 : expm1f(v3);
        } else {
            v0 = fmaxf(v0, 0.f); v1 = fmaxf(v1, 0.f);
            v2 = fmaxf(v2, 0.f); v3 = fmaxf(v3, 0.f);
            if (act >= 2){
                float s = lds(reladdr + 8u*r);
                v0 *= s; v1 *= s; v2 *= s; v3 *= s;
                if (act == 3){
                    float4 pv = ldsv4(oaddr);
                    v0 += pv.x; v1 += pv.y; v2 += pv.z; v3 += pv.w;
                }
            }
        }
        stsv4(oaddr, v0, v1, v2, v3);
    }
}

// row-offset builder; shift: 0=identity, 1=recv(+1), 5=agg(+5)
__device__ __forceinline__ Offs mk(unsigned sb, unsigned bufa, int warp, int shift){
    Offs o;
    #pragma unroll
    for (int r = 0; r < 6; ++r){
        int rr = (r + shift) % 6;
        o.a[r] = sb + bufa + (unsigned)(warp*ROWSB + rr*LDBB);
    }
    return o;
}

// ---- weight repack: [K,128] -> k-pair interleaved [K/2][128][2] ----
struct RepackArgs { const float* src[10]; int pairs[10]; int dstf4[10]; };

__global__ void repack_weights(RepackArgs A){
    int p = blockIdx.x;
    int c = 0, base = 0;
    while (p - base >= A.pairs[c]) { base += A.pairs[c]; ++c; }
    int lp = p - base;
    const float* src = A.src[c] + lp*256;       // rows 2lp, 2lp+1 of this matrix
    int t = threadIdx.x;                         // 64 threads: cols 2t, 2t+1
    float2 w0 = *reinterpret_cast<const float2*>(src + 2*t);
    float2 w1 = *reinterpret_cast<const float2*>(src + 128 + 2*t);
    float4 o; o.x = w0.x; o.y = w1.x; o.z = w0.y; o.w = w1.y;
    g_rp[A.dstf4[c] + lp*64 + t] = o;
}

__global__ void __launch_bounds__(THREADS, 2) nri_fused(Params P)
{
    extern __shared__ float sm[];
    unsigned sb = smem_u32(sm);
    const int lane = threadIdx.x & 31;
    const int warp = threadIdx.x >> 5;
    const int xbase = blockIdx.x * (TBATCH*18);
    const float* rp = reinterpret_cast<const float*>(g_rp);

    // load this warp's graph of x (18 floats)
    if (lane < 18) sm[(XSA >> 2) + warp*18 + lane] = P.x[xbase + warp*18 + lane];
    __syncwarp();

    Offs xo, xro;
    #pragma unroll
    for (int r = 0; r < 6; ++r){
        xo.a[r]  = sb + XSA + (unsigned)(warp*72 + r*12);
        xro.a[r] = sb + XSA + (unsigned)(warp*72 + ((r+1)%6)*12);
    }

    const unsigned b0w = sb + B0A + (unsigned)(warp*ROWSB);
    const unsigned b1w = sb + B1A + (unsigned)(warp*ROWSB);
    const unsigned b2w = sb + B2A + (unsigned)(warp*ROWSB);

    // ---- Encoder ----
    layer(xo, P.e1w1, 3, xo, 0, 0, P.e1b1, b0w, 0, 0u, lane); __syncwarp();
    layer(mk(sb,B0A,warp,0), rp+RPO_E1W2, 128, xo, 0, 0, P.e1b2, b1w, 0, 0u, lane); __syncwarp();
    layer(mk(sb,B1A,warp,1), rp+RPO_E2W1, 128, mk(sb,B1A,warp,0), rp+RPO_E2W1+16384, 128,
          P.e2b1, b0w, 0, 0u, lane); __syncwarp();
    layer(mk(sb,B0A,warp,0), rp+RPO_E2W2, 128, xo, 0, 0, P.e2b2, b2w, 0, 0u, lane); __syncwarp();
    layer(mk(sb,B2A,warp,0), rp+RPO_E3W1, 128, xo, 0, 0, P.e3b1, b0w, 0, 0u, lane); __syncwarp();
    layer(mk(sb,B0A,warp,0), rp+RPO_E3W2, 128, xo, 0, 0, P.e3b2, b1w, 0, 0u, lane); __syncwarp();
    layer(mk(sb,B1A,warp,0), rp+RPO_E4W1, 128, mk(sb,B2A,warp,0), rp+RPO_E4W1+16384, 128,
          P.e4b1, b0w, 0, 0u, lane); __syncwarp();
    layer(mk(sb,B0A,warp,0), rp+RPO_E4W2, 128, xo, 0, 0, P.e4b2, b1w, 0, 0u, lane); __syncwarp();

    // S5: logits -> softmax over T=2 (6 edges per warp, one lane each)
    if (lane < 6){
        unsigned hrow = sb + B1A + (unsigned)(warp*ROWSB + lane*LDBB);
        float l0 = __ldg(P.eb_out), l1 = __ldg(P.eb_out + 1);
        for (int k = 0; k < 128; ++k){
            float h = lds(hrow + 4u*k);
            l0 = fmaf(h, __ldg(P.ew_out + 2*k),     l0);
            l1 = fmaf(h, __ldg(P.ew_out + 2*k + 1), l1);
        }
        float m  = fmaxf(l0, l1);
        float e0 = __expf(l0 - m), e1 = __expf(l1 - m);
        float inv = 1.f / (e0 + e1);
        sts(sb + RSA + (unsigned)(warp*48 + lane*8),     e0*inv);
        sts(sb + RSA + (unsigned)(warp*48 + lane*8 + 4), e1*inv);
    }
    __syncwarp();

    // ---- Decoder ----
    // S6: per-type msg MLPs: pre_msg = [x_recv, x_send] -> ReLU MLP -> weighted accumulate
    for (int t = 0; t < 2; ++t){
        const float* w1t = P.dmw1 + t*768;   // [6][128]: rows 0..2 recv, rows 3..5 send
        {   // combined two small-K gemms + ReLU epilogue into B0
            ull acc[24];
            #pragma unroll
            for (int i = 0; i < 24; ++i) acc[i] = 0ull;
            unsigned ra[6];
            #pragma unroll
            for (int i = 0; i < 6; ++i) ra[i] = xro.a[i];
            gemm_small(ra, w1t, 3, acc, lane);
            #pragma unroll
            for (int i = 0; i < 6; ++i) ra[i] = xo.a[i];
            gemm_small(ra, w1t + 3*128, 3, acc, lane);
            float4 bv = __ldg(reinterpret_cast<const float4*>(P.dmb1 + t*128) + lane);
            #pragma unroll
            for (int r = 0; r < 6; ++r){
                float l0,h0,l1,h1,l2,h2,l3,h3;
                upk2(acc[r*4+0], l0, h0); upk2(acc[r*4+1], l1, h1);
                upk2(acc[r*4+2], l2, h2); upk2(acc[r*4+3], l3, h3);
                float v0 = fmaxf(l0+h0+bv.x, 0.f), v1 = fmaxf(l1+h1+bv.y, 0.f);
                float v2 = fmaxf(l2+h2+bv.z, 0.f), v3 = fmaxf(l3+h3+bv.w, 0.f);
                stsv4(b0w + (unsigned)(r*LDBB) + 16u*lane, v0, v1, v2, v3);
            }
        }
        __syncwarp();
        layer(mk(sb,B0A,warp,0), rp+RPO_DMW2 + t*16384, 128, xo, 0, 0,
              P.dmb2 + t*128, b2w, (t == 0) ? 2 : 3,
              sb + RSA + (unsigned)(warp*48 + t*4), lane); __syncwarp();
    }
    // S7: out MLP on aug=[x, agg]; agg row n = msgs row (n+5)%6
    layer(xo, P.dow1, 3, mk(sb,B2A,warp,5), rp+RPO_DOW1B, 128,
          P.dob1, b0w, 1, 0u, lane); __syncwarp();
    layer(mk(sb,B0A,warp,0), rp+RPO_DOW2, 128, xo, 0, 0, P.dob2, b1w, 1, 0u, lane); __syncwarp();

    // S8: out = x + p2 @ dow3 + dob3
    if (lane < 18){
        int r = lane / 3, c = lane - 3*r;
        unsigned prow = sb + B1A + (unsigned)(warp*ROWSB + r*LDBB);
        float acc = __ldg(P.dob3 + c);
        for (int k = 0; k < 128; ++k)
            acc = fmaf(lds(prow + 4u*k), __ldg(P.dow3 + k*3 + c), acc);
        float xv = lds(sb + XSA + (unsigned)(warp*72 + lane*4));
        P.out[xbase + warp*18 + lane] = xv + acc;
    }
}

extern "C" void kernel_launch(void* const* d_in, const int* in_sizes, int n_in,
                              void* d_out, int out_size)
{
    Params P;
    P.x     = (const float*)d_in[0];
    P.e1w1  = (const float*)d_in[3];  P.e1b1 = (const float*)d_in[4];
    P.e1w2  = (const float*)d_in[5];  P.e1b2 = (const float*)d_in[6];
    P.e2w1  = (const float*)d_in[7];  P.e2b1 = (const float*)d_in[8];
    P.e2w2  = (const float*)d_in[9];  P.e2b2 = (const float*)d_in[10];
    P.e3w1  = (const float*)d_in[11]; P.e3b1 = (const float*)d_in[12];
    P.e3w2  = (const float*)d_in[13]; P.e3b2 = (const float*)d_in[14];
    P.e4w1  = (const float*)d_in[15]; P.e4b1 = (const float*)d_in[16];
    P.e4w2  = (const float*)d_in[17]; P.e4b2 = (const float*)d_in[18];
    P.ew_out= (const float*)d_in[19]; P.eb_out=(const float*)d_in[20];
    P.dmw1  = (const float*)d_in[21]; P.dmb1 = (const float*)d_in[22];
    P.dmw2  = (const float*)d_in[23]; P.dmb2 = (const float*)d_in[24];
    P.dow1  = (const float*)d_in[25]; P.dob1 = (const float*)d_in[26];
    P.dow2  = (const float*)d_in[27]; P.dob2 = (const float*)d_in[28];
    P.dow3  = (const float*)d_in[29]; P.dob3 = (const float*)d_in[30];
    P.out   = (float*)d_out;

    // repack big-K weights into k-pair interleaved layout
    RepackArgs A;
    const float* srcs[10] = { P.e1w2, P.e2w1, P.e2w2, P.e3w1, P.e3w2,
                              P.e4w1, P.e4w2, P.dmw2, P.dow1 + 3*128, P.dow2 };
    int  prs[10] = { 64, 128, 64, 64, 64, 128, 64, 128, 64, 64 };
    int  dst[10] = { RPO_E1W2/4, RPO_E2W1/4, RPO_E2W2/4, RPO_E3W1/4, RPO_E3W2/4,
                     RPO_E4W1/4, RPO_E4W2/4, RPO_DMW2/4, RPO_DOW1B/4, RPO_DOW2/4 };
    for (int i = 0; i < 10; ++i){ A.src[i] = srcs[i]; A.pairs[i] = prs[i]; A.dstf4[i] = dst[i]; }
    repack_weights<<<832, 64>>>(A);

    int B = in_sizes[0] / 18;          // 32768
    int grid = B / TBATCH;             // 4096
    cudaFuncSetAttribute(nri_fused, cudaFuncAttributeMaxDynamicSharedMemorySize, SMEMB);
    nri_fused<<<grid, THREADS, SMEMB>>>(P);
}